// round 7
// baseline (speedup 1.0000x reference)
#include <cuda_runtime.h>
#include <cstdint>

#define B_  2
#define S_  2048
#define D_  1024
#define H_  16
#define DK_ 64
#define NEGV -1.0e9f

// Scratch (allocation-free rule: __device__ globals)
__device__ float g_q[B_ * S_ * D_];
__device__ float g_k[B_ * S_ * D_];
__device__ float g_v[B_ * S_ * D_];
__device__ float g_ctx[B_ * S_ * D_];

// ---------------------------------------------------------------------------
// GEMM: C[M,N] = A[M,K] @ B[N,K]^T + bias[N]   (fp32, NT)
// BM=BN=128, BK=16, 256 threads, 8x8 register tile per thread.
// ---------------------------------------------------------------------------
__global__ __launch_bounds__(256) void gemm_nt_bias(
    const float* __restrict__ A, const float* __restrict__ Bw,
    const float* __restrict__ bias, float* __restrict__ C,
    int M, int N, int K)
{
    const int BK = 16;
    __shared__ float As[BK][128 + 4];   // [k][m]
    __shared__ float Bs[BK][128 + 4];   // [k][n]

    const int tx = threadIdx.x, ty = threadIdx.y;
    const int tid = ty * 16 + tx;
    const int m0 = blockIdx.y * 128;
    const int n0 = blockIdx.x * 128;

    const int lr = tid >> 1;          // 0..127 (row within tile)
    const int lc = (tid & 1) * 8;     // 0 or 8 (k offset)

    float acc[8][8];
#pragma unroll
    for (int i = 0; i < 8; i++)
#pragma unroll
        for (int j = 0; j < 8; j++) acc[i][j] = 0.f;

    for (int kt = 0; kt < K; kt += BK) {
        // Stage A tile (transposed: [k][m])
        {
            const float* p = &A[(size_t)(m0 + lr) * K + kt + lc];
            float4 a0 = *(const float4*)p;
            float4 a1 = *(const float4*)(p + 4);
            As[lc + 0][lr] = a0.x; As[lc + 1][lr] = a0.y;
            As[lc + 2][lr] = a0.z; As[lc + 3][lr] = a0.w;
            As[lc + 4][lr] = a1.x; As[lc + 5][lr] = a1.y;
            As[lc + 6][lr] = a1.z; As[lc + 7][lr] = a1.w;
        }
        // Stage B tile (transposed: [k][n])
        {
            const float* p = &Bw[(size_t)(n0 + lr) * K + kt + lc];
            float4 b0 = *(const float4*)p;
            float4 b1 = *(const float4*)(p + 4);
            Bs[lc + 0][lr] = b0.x; Bs[lc + 1][lr] = b0.y;
            Bs[lc + 2][lr] = b0.z; Bs[lc + 3][lr] = b0.w;
            Bs[lc + 4][lr] = b1.x; Bs[lc + 5][lr] = b1.y;
            Bs[lc + 6][lr] = b1.z; Bs[lc + 7][lr] = b1.w;
        }
        __syncthreads();

#pragma unroll
        for (int k = 0; k < BK; k++) {
            float4 x0 = *(const float4*)&As[k][ty * 8];
            float4 x1 = *(const float4*)&As[k][ty * 8 + 4];
            float4 y0 = *(const float4*)&Bs[k][tx * 8];
            float4 y1 = *(const float4*)&Bs[k][tx * 8 + 4];
            float xa[8] = {x0.x, x0.y, x0.z, x0.w, x1.x, x1.y, x1.z, x1.w};
            float yb[8] = {y0.x, y0.y, y0.z, y0.w, y1.x, y1.y, y1.z, y1.w};
#pragma unroll
            for (int i = 0; i < 8; i++)
#pragma unroll
                for (int j = 0; j < 8; j++)
                    acc[i][j] += xa[i] * yb[j];
        }
        __syncthreads();
    }

    // Epilogue: bias + store (vectorized)
    const int nbase = n0 + tx * 8;
    float4 bi0 = *(const float4*)&bias[nbase];
    float4 bi1 = *(const float4*)&bias[nbase + 4];
    float bb[8] = {bi0.x, bi0.y, bi0.z, bi0.w, bi1.x, bi1.y, bi1.z, bi1.w};
#pragma unroll
    for (int i = 0; i < 8; i++) {
        const int row = m0 + ty * 8 + i;
        float4 c0, c1;
        c0.x = acc[i][0] + bb[0]; c0.y = acc[i][1] + bb[1];
        c0.z = acc[i][2] + bb[2]; c0.w = acc[i][3] + bb[3];
        c1.x = acc[i][4] + bb[4]; c1.y = acc[i][5] + bb[5];
        c1.z = acc[i][6] + bb[6]; c1.w = acc[i][7] + bb[7];
        *(float4*)&C[(size_t)row * N + nbase] = c0;
        *(float4*)&C[(size_t)row * N + nbase + 4] = c1;
    }
}

// ---------------------------------------------------------------------------
// Flash attention: one CTA = (b, h, 64 q-rows). Streams 64-key tiles.
// 256 threads (16x16); score tile 64x64 (4x4 regs/thread); O 64x64 (4x4/thread).
// ---------------------------------------------------------------------------
__global__ __launch_bounds__(256) void flash_kernel(
    const float* __restrict__ Q, const float* __restrict__ K,
    const float* __restrict__ V, const int* __restrict__ mask,
    float* __restrict__ ctx)
{
    const int ST = 68;  // padded stride
    extern __shared__ float sm[];
    float* Qs  = sm;             // [d][m]  64x68
    float* Kt  = Qs + 64 * ST;   // [d][n]  64x68
    float* Vs  = Kt + 64 * ST;   // [n][d]  64x68
    float* Ss  = Vs + 64 * ST;   // [m][n]  64x68
    float* m_s = Ss + 64 * ST;   // [64]
    float* l_s = m_s + 64;       // [64]
    float* al_s = l_s + 64;      // [64]

    const int tx = threadIdx.x, ty = threadIdx.y;
    const int tid = ty * 16 + tx;
    const int b = blockIdx.z, h = blockIdx.y;
    const int q0 = blockIdx.x * 64;

    const float* Qb = Q + ((size_t)b * S_ + q0) * D_ + h * DK_;
    const float* Kb = K + (size_t)b * S_ * D_ + h * DK_;
    const float* Vb = V + (size_t)b * S_ * D_ + h * DK_;
    const int*   Mb = mask + (size_t)b * S_ * S_ + (size_t)q0 * S_;

    // Load Q tile (transposed), fold 1/sqrt(dk) = 0.125
#pragma unroll 4
    for (int e = tid; e < 64 * 64; e += 256) {
        int r = e >> 6, d = e & 63;
        Qs[d * ST + r] = Qb[(size_t)r * D_ + d] * 0.125f;
    }
    if (tid < 64) { m_s[tid] = -3.0e38f; l_s[tid] = 0.f; }

    float O[4][4];
#pragma unroll
    for (int i = 0; i < 4; i++)
#pragma unroll
        for (int j = 0; j < 4; j++) O[i][j] = 0.f;

    for (int kt = 0; kt < S_; kt += 64) {
        __syncthreads();  // protect Kt/Vs from previous iteration's readers
        // Stage K (transposed) and V (natural)
#pragma unroll 4
        for (int e = tid; e < 64 * 64; e += 256) {
            int r = e >> 6, d = e & 63;
            float kval = Kb[(size_t)(kt + r) * D_ + d];
            float vval = Vb[(size_t)(kt + r) * D_ + d];
            Kt[d * ST + r] = kval;
            Vs[r * ST + d] = vval;
        }
        __syncthreads();

        // S = (Q*scale) @ K^T  — 4x4 per thread over 64-deep reduction
        float s[4][4];
#pragma unroll
        for (int i = 0; i < 4; i++)
#pragma unroll
            for (int j = 0; j < 4; j++) s[i][j] = 0.f;

#pragma unroll 8
        for (int d = 0; d < 64; d++) {
            float4 qa = *(const float4*)&Qs[d * ST + ty * 4];
            float4 kb = *(const float4*)&Kt[d * ST + tx * 4];
            float qv[4] = {qa.x, qa.y, qa.z, qa.w};
            float kv[4] = {kb.x, kb.y, kb.z, kb.w};
#pragma unroll
            for (int i = 0; i < 4; i++)
#pragma unroll
                for (int j = 0; j < 4; j++)
                    s[i][j] += qv[i] * kv[j];
        }

        // Apply mask, write score tile to smem
#pragma unroll
        for (int i = 0; i < 4; i++) {
            int m = ty * 4 + i;
            int4 mk = *(const int4*)&Mb[(size_t)m * S_ + kt + tx * 4];
            float4 w;
            w.x = mk.x ? s[i][0] : NEGV;
            w.y = mk.y ? s[i][1] : NEGV;
            w.z = mk.z ? s[i][2] : NEGV;
            w.w = mk.w ? s[i][3] : NEGV;
            *(float4*)&Ss[m * ST + tx * 4] = w;
        }
        __syncthreads();

        // Online softmax: 4 threads per row (consecutive lanes -> shfl works)
        {
            int r = tid >> 2, part = tid & 3;
            float* row = &Ss[r * ST + part * 16];
            float mx = row[0];
#pragma unroll
            for (int c = 1; c < 16; c++) mx = fmaxf(mx, row[c]);
            mx = fmaxf(mx, __shfl_xor_sync(0xffffffffu, mx, 1));
            mx = fmaxf(mx, __shfl_xor_sync(0xffffffffu, mx, 2));
            float mprev = m_s[r];
            float mnew = fmaxf(mprev, mx);
            float alpha = __expf(mprev - mnew);
            float sum = 0.f;
#pragma unroll
            for (int c = 0; c < 16; c++) {
                float p = __expf(row[c] - mnew);
                row[c] = p;
                sum += p;
            }
            sum += __shfl_xor_sync(0xffffffffu, sum, 1);
            sum += __shfl_xor_sync(0xffffffffu, sum, 2);
            if (part == 0) {
                m_s[r] = mnew;
                l_s[r] = l_s[r] * alpha + sum;
                al_s[r] = alpha;
            }
        }
        __syncthreads();

        // Rescale O, accumulate P @ V
        float al[4];
#pragma unroll
        for (int i = 0; i < 4; i++) al[i] = al_s[ty * 4 + i];
#pragma unroll
        for (int i = 0; i < 4; i++)
#pragma unroll
            for (int j = 0; j < 4; j++) O[i][j] *= al[i];

#pragma unroll 4
        for (int n = 0; n < 64; n++) {
            float4 vv = *(const float4*)&Vs[n * ST + tx * 4];
            float vb4[4] = {vv.x, vv.y, vv.z, vv.w};
            float p0 = Ss[(ty * 4 + 0) * ST + n];
            float p1 = Ss[(ty * 4 + 1) * ST + n];
            float p2 = Ss[(ty * 4 + 2) * ST + n];
            float p3 = Ss[(ty * 4 + 3) * ST + n];
#pragma unroll
            for (int j = 0; j < 4; j++) {
                O[0][j] += p0 * vb4[j];
                O[1][j] += p1 * vb4[j];
                O[2][j] += p2 * vb4[j];
                O[3][j] += p3 * vb4[j];
            }
        }
    }

    // Final normalize + store (ctx layout = concat-heads [B,S,D])
    float rinv[4];
#pragma unroll
    for (int i = 0; i < 4; i++) rinv[i] = 1.f / l_s[ty * 4 + i];
    float* Cb = ctx + ((size_t)b * S_ + q0) * D_ + h * DK_;
#pragma unroll
    for (int i = 0; i < 4; i++) {
        float4 w;
        w.x = O[i][0] * rinv[i];
        w.y = O[i][1] * rinv[i];
        w.z = O[i][2] * rinv[i];
        w.w = O[i][3] * rinv[i];
        *(float4*)&Cb[(size_t)(ty * 4 + i) * D_ + tx * 4] = w;
    }
}

// ---------------------------------------------------------------------------
// Launch
// Inputs (metadata order): query, key, value, mask, w_q, b_q, w_k, b_k,
//                          w_v, b_v, w_o, b_o
// ---------------------------------------------------------------------------
extern "C" void kernel_launch(void* const* d_in, const int* in_sizes, int n_in,
                              void* d_out, int out_size)
{
    const float* query = (const float*)d_in[0];
    const float* key   = (const float*)d_in[1];
    const float* value = (const float*)d_in[2];
    const int*   mask  = (const int*)d_in[3];
    const float* w_q = (const float*)d_in[4];
    const float* b_q = (const float*)d_in[5];
    const float* w_k = (const float*)d_in[6];
    const float* b_k = (const float*)d_in[7];
    const float* w_v = (const float*)d_in[8];
    const float* b_v = (const float*)d_in[9];
    const float* w_o = (const float*)d_in[10];
    const float* b_o = (const float*)d_in[11];

    float *gq, *gk, *gv, *gc;
    cudaGetSymbolAddress((void**)&gq, g_q);
    cudaGetSymbolAddress((void**)&gk, g_k);
    cudaGetSymbolAddress((void**)&gv, g_v);
    cudaGetSymbolAddress((void**)&gc, g_ctx);

    const size_t flash_smem = (4 * 64 * 68 + 192) * sizeof(float);  // 70400 B
    cudaFuncSetAttribute(flash_kernel,
                         cudaFuncAttributeMaxDynamicSharedMemorySize,
                         (int)flash_smem);

    dim3 blk(16, 16);
    const int M = B_ * S_;                        // 4096
    dim3 gproj(D_ / 128, M / 128);                // (8, 32)

    gemm_nt_bias<<<gproj, blk>>>(query, w_q, b_q, gq, M, D_, D_);
    gemm_nt_bias<<<gproj, blk>>>(key,   w_k, b_k, gk, M, D_, D_);
    gemm_nt_bias<<<gproj, blk>>>(value, w_v, b_v, gv, M, D_, D_);

    dim3 gflash(S_ / 64, H_, B_);                 // (32, 16, 2)
    flash_kernel<<<gflash, blk, flash_smem>>>(gq, gk, gv, mask, gc);

    gemm_nt_bias<<<gproj, blk>>>(gc, w_o, b_o, (float*)d_out, M, D_, D_);
}

// round 9
// speedup vs baseline: 1.2762x; 1.2762x over previous
#include <cuda_runtime.h>
#include <cuda_bf16.h>
#include <cstdint>

#define B_  2
#define S_  2048
#define D_  1024
#define H_  16
#define DK_ 64
#define NEGV -1.0e9f

// Scratch (allocation-free rule: __device__ globals)
__device__ float g_q[B_ * S_ * D_];
__device__ float g_k[B_ * S_ * D_];
__device__ float g_v[B_ * S_ * D_];
__device__ float g_ctx[B_ * S_ * D_];

// ===========================================================================
// bf16 HMMA GEMM: C[M,N] = A[M,K] @ B[N,K]^T + bias[N]
// mma.sync.m16n8k16 (compute_103-legal), 3-term hi/lo bf16 split for fp32
// accuracy. CTA tile 128x128, K-chunk 32, 8 warps (4x2 warp grid, 32x64 each).
// smem stride 40 bf16 (80 B) -> conflict-free fragment LDS.
// ===========================================================================
#define MMA16816(c, a, b) \
    asm volatile("mma.sync.aligned.m16n8k16.row.col.f32.bf16.bf16.f32 " \
        "{%0,%1,%2,%3}, {%4,%5,%6,%7}, {%8,%9}, {%0,%1,%2,%3};" \
        : "+f"((c)[0]), "+f"((c)[1]), "+f"((c)[2]), "+f"((c)[3]) \
        : "r"((a)[0]), "r"((a)[1]), "r"((a)[2]), "r"((a)[3]), \
          "r"((b)[0]), "r"((b)[1]))

#define GSTRIDE 80              // bytes per smem row (40 bf16)
#define OFF_AH 0
#define OFF_AL (128 * GSTRIDE)
#define OFF_BH (2 * 128 * GSTRIDE)
#define OFF_BL (3 * 128 * GSTRIDE)
#define GEMM_SMEM (4 * 128 * GSTRIDE)   // 40960 B

// Convert 16 fp32 (in 4 float4 regs) -> 16 bf16 hi + 16 bf16 lo, store to smem.
__device__ __forceinline__ void store_split16(
    const float4* v, char* hi, char* lo, uint32_t boff)
{
    uint32_t hw[8], lw[8];
#pragma unroll
    for (int q = 0; q < 4; q++) {
        float x[4] = {v[q].x, v[q].y, v[q].z, v[q].w};
#pragma unroll
        for (int p = 0; p < 2; p++) {
            float x0 = x[2 * p], x1 = x[2 * p + 1];
            __nv_bfloat16 h0 = __float2bfloat16_rn(x0);
            __nv_bfloat16 h1 = __float2bfloat16_rn(x1);
            __nv_bfloat16 l0 = __float2bfloat16_rn(x0 - __bfloat162float(h0));
            __nv_bfloat16 l1 = __float2bfloat16_rn(x1 - __bfloat162float(h1));
            hw[q * 2 + p] = (uint32_t)__bfloat16_as_ushort(h0) |
                            ((uint32_t)__bfloat16_as_ushort(h1) << 16);
            lw[q * 2 + p] = (uint32_t)__bfloat16_as_ushort(l0) |
                            ((uint32_t)__bfloat16_as_ushort(l1) << 16);
        }
    }
    *(uint4*)(hi + boff)      = make_uint4(hw[0], hw[1], hw[2], hw[3]);
    *(uint4*)(hi + boff + 16) = make_uint4(hw[4], hw[5], hw[6], hw[7]);
    *(uint4*)(lo + boff)      = make_uint4(lw[0], lw[1], lw[2], lw[3]);
    *(uint4*)(lo + boff + 16) = make_uint4(lw[4], lw[5], lw[6], lw[7]);
}

__global__ __launch_bounds__(256) void gemm_tc(
    const float* __restrict__ A, const float* __restrict__ Bw,
    const float* __restrict__ bias, float* __restrict__ C,
    int M, int N, int K)
{
    extern __shared__ char smc[];
    char* AH = smc + OFF_AH;
    char* AL = smc + OFF_AL;
    char* BH = smc + OFF_BH;
    char* BL = smc + OFF_BL;

    const int tid = threadIdx.x;
    const int wid = tid >> 5, lane = tid & 31;
    const int g = lane >> 2, t = lane & 3;
    const int warp_m = wid & 3;     // 0..3 -> 32 rows each
    const int warp_n = wid >> 2;    // 0..1 -> 64 cols each
    const int m0 = blockIdx.y * 128;
    const int n0 = blockIdx.x * 128;

    // Staging assignment: thread = (row r, half h), 16 contiguous floats.
    const int r = tid >> 1, h = tid & 1;
    const float* gA = A + (size_t)(m0 + r) * K + h * 16;
    const float* gB = Bw + (size_t)(n0 + r) * K + h * 16;
    const uint32_t boff = (uint32_t)r * GSTRIDE + h * 32;

    float acc[2][8][4];
#pragma unroll
    for (int mi = 0; mi < 2; mi++)
#pragma unroll
        for (int ni = 0; ni < 8; ni++)
#pragma unroll
            for (int c = 0; c < 4; c++) acc[mi][ni][c] = 0.f;

    // Prefetch chunk 0
    float4 vA[4], vB[4];
#pragma unroll
    for (int q = 0; q < 4; q++) {
        vA[q] = *(const float4*)(gA + q * 4);
        vB[q] = *(const float4*)(gB + q * 4);
    }

    const int nchunks = K / 32;
    for (int ck = 0; ck < nchunks; ck++) {
        __syncthreads();   // previous chunk's MMAs done before overwrite
        store_split16(vA, AH, AL, boff);
        store_split16(vB, BH, BL, boff);
        __syncthreads();

        if (ck + 1 < nchunks) {
            const float* pa = gA + (ck + 1) * 32;
            const float* pb = gB + (ck + 1) * 32;
#pragma unroll
            for (int q = 0; q < 4; q++) {
                vA[q] = *(const float4*)(pa + q * 4);
                vB[q] = *(const float4*)(pb + q * 4);
            }
        }

#pragma unroll
        for (int ks = 0; ks < 2; ks++) {
            const uint32_t ko = (uint32_t)(ks * 16 + t * 2) * 2;

            uint32_t ah[2][4], alr[2][4];
#pragma unroll
            for (int mi = 0; mi < 2; mi++) {
                const uint32_t o = (uint32_t)(warp_m * 32 + mi * 16 + g) * GSTRIDE + ko;
                ah[mi][0]  = *(const uint32_t*)(AH + o);
                ah[mi][1]  = *(const uint32_t*)(AH + o + 8 * GSTRIDE);
                ah[mi][2]  = *(const uint32_t*)(AH + o + 16);
                ah[mi][3]  = *(const uint32_t*)(AH + o + 8 * GSTRIDE + 16);
                alr[mi][0] = *(const uint32_t*)(AL + o);
                alr[mi][1] = *(const uint32_t*)(AL + o + 8 * GSTRIDE);
                alr[mi][2] = *(const uint32_t*)(AL + o + 16);
                alr[mi][3] = *(const uint32_t*)(AL + o + 8 * GSTRIDE + 16);
            }

            uint32_t bh[8][2], bl[8][2];
#pragma unroll
            for (int ni = 0; ni < 8; ni++) {
                const uint32_t o = (uint32_t)(warp_n * 64 + ni * 8 + g) * GSTRIDE + ko;
                bh[ni][0] = *(const uint32_t*)(BH + o);
                bh[ni][1] = *(const uint32_t*)(BH + o + 16);
                bl[ni][0] = *(const uint32_t*)(BL + o);
                bl[ni][1] = *(const uint32_t*)(BL + o + 16);
            }

#pragma unroll
            for (int mi = 0; mi < 2; mi++)
#pragma unroll
                for (int ni = 0; ni < 8; ni++) {
                    MMA16816(acc[mi][ni], ah[mi], bh[ni]);
                    MMA16816(acc[mi][ni], ah[mi], bl[ni]);
                    MMA16816(acc[mi][ni], alr[mi], bh[ni]);
                }
        }
    }

    // Epilogue: bias + fp32 store
#pragma unroll
    for (int mi = 0; mi < 2; mi++) {
        const int row0 = m0 + warp_m * 32 + mi * 16 + g;
#pragma unroll
        for (int ni = 0; ni < 8; ni++) {
            const int col = n0 + warp_n * 64 + ni * 8 + t * 2;
            float2 bi = *(const float2*)&bias[col];
            float2 o0, o1;
            o0.x = acc[mi][ni][0] + bi.x;
            o0.y = acc[mi][ni][1] + bi.y;
            o1.x = acc[mi][ni][2] + bi.x;
            o1.y = acc[mi][ni][3] + bi.y;
            *(float2*)&C[(size_t)row0 * N + col] = o0;
            *(float2*)&C[(size_t)(row0 + 8) * N + col] = o1;
        }
    }
}

// ---------------------------------------------------------------------------
// Flash attention (unchanged from R7 passing version)
// ---------------------------------------------------------------------------
__global__ __launch_bounds__(256) void flash_kernel(
    const float* __restrict__ Q, const float* __restrict__ K,
    const float* __restrict__ V, const int* __restrict__ mask,
    float* __restrict__ ctx)
{
    const int ST = 68;
    extern __shared__ float sm[];
    float* Qs  = sm;
    float* Kt  = Qs + 64 * ST;
    float* Vs  = Kt + 64 * ST;
    float* Ss  = Vs + 64 * ST;
    float* m_s = Ss + 64 * ST;
    float* l_s = m_s + 64;
    float* al_s = l_s + 64;

    const int tx = threadIdx.x, ty = threadIdx.y;
    const int tid = ty * 16 + tx;
    const int b = blockIdx.z, h = blockIdx.y;
    const int q0 = blockIdx.x * 64;

    const float* Qb = Q + ((size_t)b * S_ + q0) * D_ + h * DK_;
    const float* Kb = K + (size_t)b * S_ * D_ + h * DK_;
    const float* Vb = V + (size_t)b * S_ * D_ + h * DK_;
    const int*   Mb = mask + (size_t)b * S_ * S_ + (size_t)q0 * S_;

#pragma unroll 4
    for (int e = tid; e < 64 * 64; e += 256) {
        int r = e >> 6, d = e & 63;
        Qs[d * ST + r] = Qb[(size_t)r * D_ + d] * 0.125f;
    }
    if (tid < 64) { m_s[tid] = -3.0e38f; l_s[tid] = 0.f; }

    float O[4][4];
#pragma unroll
    for (int i = 0; i < 4; i++)
#pragma unroll
        for (int j = 0; j < 4; j++) O[i][j] = 0.f;

    for (int kt = 0; kt < S_; kt += 64) {
        __syncthreads();
#pragma unroll 4
        for (int e = tid; e < 64 * 64; e += 256) {
            int r = e >> 6, d = e & 63;
            float kval = Kb[(size_t)(kt + r) * D_ + d];
            float vval = Vb[(size_t)(kt + r) * D_ + d];
            Kt[d * ST + r] = kval;
            Vs[r * ST + d] = vval;
        }
        __syncthreads();

        float s[4][4];
#pragma unroll
        for (int i = 0; i < 4; i++)
#pragma unroll
            for (int j = 0; j < 4; j++) s[i][j] = 0.f;

#pragma unroll 8
        for (int d = 0; d < 64; d++) {
            float4 qa = *(const float4*)&Qs[d * ST + ty * 4];
            float4 kb = *(const float4*)&Kt[d * ST + tx * 4];
            float qv[4] = {qa.x, qa.y, qa.z, qa.w};
            float kv[4] = {kb.x, kb.y, kb.z, kb.w};
#pragma unroll
            for (int i = 0; i < 4; i++)
#pragma unroll
                for (int j = 0; j < 4; j++)
                    s[i][j] += qv[i] * kv[j];
        }

#pragma unroll
        for (int i = 0; i < 4; i++) {
            int m = ty * 4 + i;
            int4 mk = *(const int4*)&Mb[(size_t)m * S_ + kt + tx * 4];
            float4 w;
            w.x = mk.x ? s[i][0] : NEGV;
            w.y = mk.y ? s[i][1] : NEGV;
            w.z = mk.z ? s[i][2] : NEGV;
            w.w = mk.w ? s[i][3] : NEGV;
            *(float4*)&Ss[m * ST + tx * 4] = w;
        }
        __syncthreads();

        {
            int r = tid >> 2, part = tid & 3;
            float* row = &Ss[r * ST + part * 16];
            float mx = row[0];
#pragma unroll
            for (int c = 1; c < 16; c++) mx = fmaxf(mx, row[c]);
            mx = fmaxf(mx, __shfl_xor_sync(0xffffffffu, mx, 1));
            mx = fmaxf(mx, __shfl_xor_sync(0xffffffffu, mx, 2));
            float mprev = m_s[r];
            float mnew = fmaxf(mprev, mx);
            float alpha = __expf(mprev - mnew);
            float sum = 0.f;
#pragma unroll
            for (int c = 0; c < 16; c++) {
                float p = __expf(row[c] - mnew);
                row[c] = p;
                sum += p;
            }
            sum += __shfl_xor_sync(0xffffffffu, sum, 1);
            sum += __shfl_xor_sync(0xffffffffu, sum, 2);
            if (part == 0) {
                m_s[r] = mnew;
                l_s[r] = l_s[r] * alpha + sum;
                al_s[r] = alpha;
            }
        }
        __syncthreads();

        float al[4];
#pragma unroll
        for (int i = 0; i < 4; i++) al[i] = al_s[ty * 4 + i];
#pragma unroll
        for (int i = 0; i < 4; i++)
#pragma unroll
            for (int j = 0; j < 4; j++) O[i][j] *= al[i];

#pragma unroll 4
        for (int n = 0; n < 64; n++) {
            float4 vv = *(const float4*)&Vs[n * ST + tx * 4];
            float vb4[4] = {vv.x, vv.y, vv.z, vv.w};
            float p0 = Ss[(ty * 4 + 0) * ST + n];
            float p1 = Ss[(ty * 4 + 1) * ST + n];
            float p2 = Ss[(ty * 4 + 2) * ST + n];
            float p3 = Ss[(ty * 4 + 3) * ST + n];
#pragma unroll
            for (int j = 0; j < 4; j++) {
                O[0][j] += p0 * vb4[j];
                O[1][j] += p1 * vb4[j];
                O[2][j] += p2 * vb4[j];
                O[3][j] += p3 * vb4[j];
            }
        }
    }

    float rinv[4];
#pragma unroll
    for (int i = 0; i < 4; i++) rinv[i] = 1.f / l_s[ty * 4 + i];
    float* Cb = ctx + ((size_t)b * S_ + q0) * D_ + h * DK_;
#pragma unroll
    for (int i = 0; i < 4; i++) {
        float4 w;
        w.x = O[i][0] * rinv[i];
        w.y = O[i][1] * rinv[i];
        w.z = O[i][2] * rinv[i];
        w.w = O[i][3] * rinv[i];
        *(float4*)&Cb[(size_t)(ty * 4 + i) * D_ + tx * 4] = w;
    }
}

// ---------------------------------------------------------------------------
// Launch
// ---------------------------------------------------------------------------
extern "C" void kernel_launch(void* const* d_in, const int* in_sizes, int n_in,
                              void* d_out, int out_size)
{
    const float* query = (const float*)d_in[0];
    const float* key   = (const float*)d_in[1];
    const float* value = (const float*)d_in[2];
    const int*   mask  = (const int*)d_in[3];
    const float* w_q = (const float*)d_in[4];
    const float* b_q = (const float*)d_in[5];
    const float* w_k = (const float*)d_in[6];
    const float* b_k = (const float*)d_in[7];
    const float* w_v = (const float*)d_in[8];
    const float* b_v = (const float*)d_in[9];
    const float* w_o = (const float*)d_in[10];
    const float* b_o = (const float*)d_in[11];

    float *gq, *gk, *gv, *gc;
    cudaGetSymbolAddress((void**)&gq, g_q);
    cudaGetSymbolAddress((void**)&gk, g_k);
    cudaGetSymbolAddress((void**)&gv, g_v);
    cudaGetSymbolAddress((void**)&gc, g_ctx);

    const size_t flash_smem = (4 * 64 * 68 + 192) * sizeof(float);  // 70400 B
    cudaFuncSetAttribute(flash_kernel,
                         cudaFuncAttributeMaxDynamicSharedMemorySize,
                         (int)flash_smem);

    const int M = B_ * S_;                        // 4096
    dim3 gproj(D_ / 128, M / 128);                // (8, 32) = 256 CTAs

    gemm_tc<<<gproj, 256, GEMM_SMEM>>>(query, w_q, b_q, gq, M, D_, D_);
    gemm_tc<<<gproj, 256, GEMM_SMEM>>>(key,   w_k, b_k, gk, M, D_, D_);
    gemm_tc<<<gproj, 256, GEMM_SMEM>>>(value, w_v, b_v, gv, M, D_, D_);

    dim3 blk(16, 16);
    dim3 gflash(S_ / 64, H_, B_);                 // (32, 16, 2)
    flash_kernel<<<gflash, blk, flash_smem>>>(gq, gk, gv, mask, gc);

    gemm_tc<<<gproj, 256, GEMM_SMEM>>>(gc, w_o, b_o, (float*)d_out, M, D_, D_);
}

// round 10
// speedup vs baseline: 1.8316x; 1.4351x over previous
#include <cuda_runtime.h>
#include <cuda_bf16.h>
#include <cstdint>

#define B_  2
#define S_  2048
#define D_  1024
#define H_  16
#define DK_ 64
#define NEGV -1.0e9f

// Scratch (allocation-free rule: __device__ globals)
__device__ float g_q[B_ * S_ * D_];
__device__ float g_k[B_ * S_ * D_];
__device__ float g_v[B_ * S_ * D_];
__device__ float g_ctx[B_ * S_ * D_];

// ===========================================================================
// Common helpers
// ===========================================================================
#define MMA16816(c, a, b) \
    asm volatile("mma.sync.aligned.m16n8k16.row.col.f32.bf16.bf16.f32 " \
        "{%0,%1,%2,%3}, {%4,%5,%6,%7}, {%8,%9}, {%0,%1,%2,%3};" \
        : "+f"((c)[0]), "+f"((c)[1]), "+f"((c)[2]), "+f"((c)[3]) \
        : "r"((a)[0]), "r"((a)[1]), "r"((a)[2]), "r"((a)[3]), \
          "r"((b)[0]), "r"((b)[1]))

__device__ __forceinline__ uint32_t pack2bf(__nv_bfloat16 a, __nv_bfloat16 b) {
    return (uint32_t)__bfloat16_as_ushort(a) |
           ((uint32_t)__bfloat16_as_ushort(b) << 16);
}

// Convert 16 fp32 (4 float4) -> 16 bf16 hi + 16 bf16 lo, store 2 uint4 each.
__device__ __forceinline__ void store_split16(
    const float4* v, char* hi, char* lo, uint32_t boff)
{
    uint32_t hw[8], lw[8];
#pragma unroll
    for (int q = 0; q < 4; q++) {
        float x[4] = {v[q].x, v[q].y, v[q].z, v[q].w};
#pragma unroll
        for (int p = 0; p < 2; p++) {
            float x0 = x[2 * p], x1 = x[2 * p + 1];
            __nv_bfloat16 h0 = __float2bfloat16_rn(x0);
            __nv_bfloat16 h1 = __float2bfloat16_rn(x1);
            __nv_bfloat16 l0 = __float2bfloat16_rn(x0 - __bfloat162float(h0));
            __nv_bfloat16 l1 = __float2bfloat16_rn(x1 - __bfloat162float(h1));
            hw[q * 2 + p] = pack2bf(h0, h1);
            lw[q * 2 + p] = pack2bf(l0, l1);
        }
    }
    *(uint4*)(hi + boff)      = make_uint4(hw[0], hw[1], hw[2], hw[3]);
    *(uint4*)(hi + boff + 16) = make_uint4(hw[4], hw[5], hw[6], hw[7]);
    *(uint4*)(lo + boff)      = make_uint4(lw[0], lw[1], lw[2], lw[3]);
    *(uint4*)(lo + boff + 16) = make_uint4(lw[4], lw[5], lw[6], lw[7]);
}

// ===========================================================================
// bf16 HMMA GEMM (unchanged from R9 passing version)
// ===========================================================================
#define GSTRIDE 80
#define OFF_AH 0
#define OFF_AL (128 * GSTRIDE)
#define OFF_BH (2 * 128 * GSTRIDE)
#define OFF_BL (3 * 128 * GSTRIDE)
#define GEMM_SMEM (4 * 128 * GSTRIDE)   // 40960 B

__global__ __launch_bounds__(256) void gemm_tc(
    const float* __restrict__ A, const float* __restrict__ Bw,
    const float* __restrict__ bias, float* __restrict__ C,
    int M, int N, int K)
{
    extern __shared__ char smc[];
    char* AH = smc + OFF_AH;
    char* AL = smc + OFF_AL;
    char* BH = smc + OFF_BH;
    char* BL = smc + OFF_BL;

    const int tid = threadIdx.x;
    const int wid = tid >> 5, lane = tid & 31;
    const int g = lane >> 2, t = lane & 3;
    const int warp_m = wid & 3;
    const int warp_n = wid >> 2;
    const int m0 = blockIdx.y * 128;
    const int n0 = blockIdx.x * 128;

    const int r = tid >> 1, h = tid & 1;
    const float* gA = A + (size_t)(m0 + r) * K + h * 16;
    const float* gB = Bw + (size_t)(n0 + r) * K + h * 16;
    const uint32_t boff = (uint32_t)r * GSTRIDE + h * 32;

    float acc[2][8][4];
#pragma unroll
    for (int mi = 0; mi < 2; mi++)
#pragma unroll
        for (int ni = 0; ni < 8; ni++)
#pragma unroll
            for (int c = 0; c < 4; c++) acc[mi][ni][c] = 0.f;

    float4 vA[4], vB[4];
#pragma unroll
    for (int q = 0; q < 4; q++) {
        vA[q] = *(const float4*)(gA + q * 4);
        vB[q] = *(const float4*)(gB + q * 4);
    }

    const int nchunks = K / 32;
    for (int ck = 0; ck < nchunks; ck++) {
        __syncthreads();
        store_split16(vA, AH, AL, boff);
        store_split16(vB, BH, BL, boff);
        __syncthreads();

        if (ck + 1 < nchunks) {
            const float* pa = gA + (ck + 1) * 32;
            const float* pb = gB + (ck + 1) * 32;
#pragma unroll
            for (int q = 0; q < 4; q++) {
                vA[q] = *(const float4*)(pa + q * 4);
                vB[q] = *(const float4*)(pb + q * 4);
            }
        }

#pragma unroll
        for (int ks = 0; ks < 2; ks++) {
            const uint32_t ko = (uint32_t)(ks * 16 + t * 2) * 2;

            uint32_t ah[2][4], alr[2][4];
#pragma unroll
            for (int mi = 0; mi < 2; mi++) {
                const uint32_t o = (uint32_t)(warp_m * 32 + mi * 16 + g) * GSTRIDE + ko;
                ah[mi][0]  = *(const uint32_t*)(AH + o);
                ah[mi][1]  = *(const uint32_t*)(AH + o + 8 * GSTRIDE);
                ah[mi][2]  = *(const uint32_t*)(AH + o + 16);
                ah[mi][3]  = *(const uint32_t*)(AH + o + 8 * GSTRIDE + 16);
                alr[mi][0] = *(const uint32_t*)(AL + o);
                alr[mi][1] = *(const uint32_t*)(AL + o + 8 * GSTRIDE);
                alr[mi][2] = *(const uint32_t*)(AL + o + 16);
                alr[mi][3] = *(const uint32_t*)(AL + o + 8 * GSTRIDE + 16);
            }

            uint32_t bh[8][2], bl[8][2];
#pragma unroll
            for (int ni = 0; ni < 8; ni++) {
                const uint32_t o = (uint32_t)(warp_n * 64 + ni * 8 + g) * GSTRIDE + ko;
                bh[ni][0] = *(const uint32_t*)(BH + o);
                bh[ni][1] = *(const uint32_t*)(BH + o + 16);
                bl[ni][0] = *(const uint32_t*)(BL + o);
                bl[ni][1] = *(const uint32_t*)(BL + o + 16);
            }

#pragma unroll
            for (int mi = 0; mi < 2; mi++)
#pragma unroll
                for (int ni = 0; ni < 8; ni++) {
                    MMA16816(acc[mi][ni], ah[mi], bh[ni]);
                    MMA16816(acc[mi][ni], ah[mi], bl[ni]);
                    MMA16816(acc[mi][ni], alr[mi], bh[ni]);
                }
        }
    }

#pragma unroll
    for (int mi = 0; mi < 2; mi++) {
        const int row0 = m0 + warp_m * 32 + mi * 16 + g;
#pragma unroll
        for (int ni = 0; ni < 8; ni++) {
            const int col = n0 + warp_n * 64 + ni * 8 + t * 2;
            float2 bi = *(const float2*)&bias[col];
            float2 o0, o1;
            o0.x = acc[mi][ni][0] + bi.x;
            o0.y = acc[mi][ni][1] + bi.y;
            o1.x = acc[mi][ni][2] + bi.x;
            o1.y = acc[mi][ni][3] + bi.y;
            *(float2*)&C[(size_t)row0 * N + col] = o0;
            *(float2*)&C[(size_t)(row0 + 8) * N + col] = o1;
        }
    }
}

// ===========================================================================
// Tensor-core flash attention.
// CTA = 128 q-rows x one (b,h). 8 warps, each owns 16 full q-rows.
// QK^T and PV on mma.sync bf16 with 3-term hi/lo split.
// Scores stay in registers (C-frag of QK == A-frag of PV).
// ===========================================================================
#define FST 72                         // bf16 elems per smem row
#define FSTB 144                       // bytes per smem row
#define FQ_H 0
#define FQ_L (128 * FSTB)              // 18432
#define FK_H (2 * 128 * FSTB)          // 36864
#define FK_L (FK_H + 64 * FSTB)        // 46080
#define FV_H (FK_L + 64 * FSTB)        // 55296
#define FV_L (FV_H + 64 * FSTB)        // 64512
#define FLASH_SMEM (FV_L + 64 * FSTB)  // 73728

__global__ __launch_bounds__(256, 1) void flash_tc(
    const float* __restrict__ Q, const float* __restrict__ K,
    const float* __restrict__ V, const int* __restrict__ mask,
    float* __restrict__ ctx)
{
    extern __shared__ char smf[];
    const int tid = threadIdx.x;
    const int wid = tid >> 5, lane = tid & 31;
    const int g = lane >> 2, t = lane & 3;
    const int b = blockIdx.z, h = blockIdx.y;
    const int q0 = blockIdx.x * 128;

    const float* Qb = Q + ((size_t)b * S_ + q0) * D_ + h * DK_;
    const float* Kb = K + (size_t)b * S_ * D_ + h * DK_;
    const float* Vb = V + (size_t)b * S_ * D_ + h * DK_;
    const int*   Mb = mask + (size_t)b * S_ * S_;

    // ---- Stage Q once: scale 0.125, split hi/lo ----
    {
        const int r = tid >> 1, hf = tid & 1;
        const float* src = Qb + (size_t)r * D_ + hf * 32;
#pragma unroll
        for (int seg = 0; seg < 2; seg++) {
            float4 v[4];
#pragma unroll
            for (int j = 0; j < 4; j++) {
                float4 x = *(const float4*)(src + seg * 16 + j * 4);
                x.x *= 0.125f; x.y *= 0.125f; x.z *= 0.125f; x.w *= 0.125f;
                v[j] = x;
            }
            store_split16(v, smf + FQ_H, smf + FQ_L,
                          (uint32_t)r * FSTB + hf * 64 + seg * 32);
        }
    }
    __syncthreads();

    // ---- Hoist Q fragments to registers (whole-kernel reuse) ----
    uint32_t qh[4][4], ql[4][4];
    {
        const uint32_t rowb = (uint32_t)(wid * 16 + g) * FSTB + (uint32_t)t * 4;
#pragma unroll
        for (int ks = 0; ks < 4; ks++) {
            const uint32_t o = rowb + ks * 32;
            qh[ks][0] = *(const uint32_t*)(smf + FQ_H + o);
            qh[ks][1] = *(const uint32_t*)(smf + FQ_H + o + 8 * FSTB);
            qh[ks][2] = *(const uint32_t*)(smf + FQ_H + o + 16);
            qh[ks][3] = *(const uint32_t*)(smf + FQ_H + o + 8 * FSTB + 16);
            ql[ks][0] = *(const uint32_t*)(smf + FQ_L + o);
            ql[ks][1] = *(const uint32_t*)(smf + FQ_L + o + 8 * FSTB);
            ql[ks][2] = *(const uint32_t*)(smf + FQ_L + o + 16);
            ql[ks][3] = *(const uint32_t*)(smf + FQ_L + o + 8 * FSTB + 16);
        }
    }

    float O[8][4];
#pragma unroll
    for (int ni = 0; ni < 8; ni++)
#pragma unroll
        for (int c = 0; c < 4; c++) O[ni][c] = 0.f;

    float m0r = -3.0e38f, m1r = -3.0e38f;
    float l0r = 0.f, l1r = 0.f;

    const int r0g = q0 + wid * 16 + g;      // global q row (c0,c1)
    const int r1g = r0g + 8;                // global q row (c2,c3)

    // K/V staging assignment: row kr, col segment cs (16 floats)
    const int kr = tid >> 2;
    const int cs = (tid & 3) * 16;

    for (int kt = 0; kt < S_; kt += 64) {
        __syncthreads();   // prior tile's fragment reads complete
        // ---- Stage K (natural [key][dk]) and V (transposed [dk][key]) ----
        {
            const float* srcK = Kb + (size_t)(kt + kr) * D_ + cs;
            float4 v[4];
#pragma unroll
            for (int j = 0; j < 4; j++) v[j] = *(const float4*)(srcK + j * 4);
            store_split16(v, smf + FK_H, smf + FK_L,
                          (uint32_t)kr * FSTB + cs * 2);

            const float* srcV = Vb + (size_t)(kt + kr) * D_ + cs;
            float vv[16];
#pragma unroll
            for (int j = 0; j < 4; j++) {
                float4 x = *(const float4*)(srcV + j * 4);
                vv[j * 4 + 0] = x.x; vv[j * 4 + 1] = x.y;
                vv[j * 4 + 2] = x.z; vv[j * 4 + 3] = x.w;
            }
#pragma unroll
            for (int j = 0; j < 16; j++) {
                __nv_bfloat16 hb = __float2bfloat16_rn(vv[j]);
                __nv_bfloat16 lb = __float2bfloat16_rn(vv[j] - __bfloat162float(hb));
                const uint32_t o = (uint32_t)(cs + j) * FSTB + kr * 2;
                *(__nv_bfloat16*)(smf + FV_H + o) = hb;
                *(__nv_bfloat16*)(smf + FV_L + o) = lb;
            }
        }
        __syncthreads();

        // ---- S = (Q*0.125) @ K^T  (3-term split) ----
        float s[8][4];
#pragma unroll
        for (int ni = 0; ni < 8; ni++) {
#pragma unroll
            for (int c = 0; c < 4; c++) s[ni][c] = 0.f;
            const uint32_t rb = (uint32_t)(ni * 8 + g) * FSTB + (uint32_t)t * 4;
#pragma unroll
            for (int ks = 0; ks < 4; ks++) {
                const uint32_t o = rb + ks * 32;
                uint32_t kbh[2], kbl[2];
                kbh[0] = *(const uint32_t*)(smf + FK_H + o);
                kbh[1] = *(const uint32_t*)(smf + FK_H + o + 16);
                kbl[0] = *(const uint32_t*)(smf + FK_L + o);
                kbl[1] = *(const uint32_t*)(smf + FK_L + o + 16);
                MMA16816(s[ni], qh[ks], kbh);
                MMA16816(s[ni], qh[ks], kbl);
                MMA16816(s[ni], ql[ks], kbh);
            }
        }

        // ---- Mask ----
#pragma unroll
        for (int ni = 0; ni < 8; ni++) {
            const int c = kt + ni * 8 + t * 2;
            int2 mk0 = *(const int2*)(Mb + (size_t)r0g * S_ + c);
            int2 mk1 = *(const int2*)(Mb + (size_t)r1g * S_ + c);
            if (!mk0.x) s[ni][0] = NEGV;
            if (!mk0.y) s[ni][1] = NEGV;
            if (!mk1.x) s[ni][2] = NEGV;
            if (!mk1.y) s[ni][3] = NEGV;
        }

        // ---- Online softmax (within t-quad) ----
        float mx0 = s[0][0], mx1 = s[0][2];
#pragma unroll
        for (int ni = 0; ni < 8; ni++) {
            mx0 = fmaxf(mx0, fmaxf(s[ni][0], s[ni][1]));
            mx1 = fmaxf(mx1, fmaxf(s[ni][2], s[ni][3]));
        }
        mx0 = fmaxf(mx0, __shfl_xor_sync(0xffffffffu, mx0, 1));
        mx0 = fmaxf(mx0, __shfl_xor_sync(0xffffffffu, mx0, 2));
        mx1 = fmaxf(mx1, __shfl_xor_sync(0xffffffffu, mx1, 1));
        mx1 = fmaxf(mx1, __shfl_xor_sync(0xffffffffu, mx1, 2));

        const float mn0 = fmaxf(m0r, mx0);
        const float mn1 = fmaxf(m1r, mx1);
        const float a0 = __expf(m0r - mn0);
        const float a1 = __expf(m1r - mn1);
        m0r = mn0; m1r = mn1;

        float sum0 = 0.f, sum1 = 0.f;
#pragma unroll
        for (int ni = 0; ni < 8; ni++) {
            s[ni][0] = __expf(s[ni][0] - mn0);
            s[ni][1] = __expf(s[ni][1] - mn0);
            s[ni][2] = __expf(s[ni][2] - mn1);
            s[ni][3] = __expf(s[ni][3] - mn1);
            sum0 += s[ni][0] + s[ni][1];
            sum1 += s[ni][2] + s[ni][3];
        }
        sum0 += __shfl_xor_sync(0xffffffffu, sum0, 1);
        sum0 += __shfl_xor_sync(0xffffffffu, sum0, 2);
        sum1 += __shfl_xor_sync(0xffffffffu, sum1, 1);
        sum1 += __shfl_xor_sync(0xffffffffu, sum1, 2);
        l0r = l0r * a0 + sum0;
        l1r = l1r * a1 + sum1;

#pragma unroll
        for (int ni = 0; ni < 8; ni++) {
            O[ni][0] *= a0; O[ni][1] *= a0;
            O[ni][2] *= a1; O[ni][3] *= a1;
        }

        // ---- PV: O += P @ V  (P from S regs, 3-term split) ----
#pragma unroll
        for (int ksp = 0; ksp < 4; ksp++) {
            uint32_t pah[4], pal[4];
#pragma unroll
            for (int hf = 0; hf < 2; hf++) {
                const float* p = s[2 * ksp + hf];
                __nv_bfloat16 h0 = __float2bfloat16_rn(p[0]);
                __nv_bfloat16 h1 = __float2bfloat16_rn(p[1]);
                __nv_bfloat16 h2 = __float2bfloat16_rn(p[2]);
                __nv_bfloat16 h3 = __float2bfloat16_rn(p[3]);
                __nv_bfloat16 l0 = __float2bfloat16_rn(p[0] - __bfloat162float(h0));
                __nv_bfloat16 l1 = __float2bfloat16_rn(p[1] - __bfloat162float(h1));
                __nv_bfloat16 l2 = __float2bfloat16_rn(p[2] - __bfloat162float(h2));
                __nv_bfloat16 l3 = __float2bfloat16_rn(p[3] - __bfloat162float(h3));
                pah[hf * 2 + 0] = pack2bf(h0, h1);
                pah[hf * 2 + 1] = pack2bf(h2, h3);
                pal[hf * 2 + 0] = pack2bf(l0, l1);
                pal[hf * 2 + 1] = pack2bf(l2, l3);
            }
#pragma unroll
            for (int ni = 0; ni < 8; ni++) {
                const uint32_t o = (uint32_t)(ni * 8 + g) * FSTB +
                                   (uint32_t)(ksp * 16 + t * 2) * 2;
                uint32_t vbh[2], vbl[2];
                vbh[0] = *(const uint32_t*)(smf + FV_H + o);
                vbh[1] = *(const uint32_t*)(smf + FV_H + o + 16);
                vbl[0] = *(const uint32_t*)(smf + FV_L + o);
                vbl[1] = *(const uint32_t*)(smf + FV_L + o + 16);
                MMA16816(O[ni], pah, vbh);
                MMA16816(O[ni], pah, vbl);
                MMA16816(O[ni], pal, vbh);
            }
        }
    }

    // ---- Final normalize + store ----
    const float ri0 = 1.f / l0r;
    const float ri1 = 1.f / l1r;
    float* C0 = ctx + ((size_t)b * S_ + r0g) * D_ + h * DK_;
    float* C1 = ctx + ((size_t)b * S_ + r1g) * D_ + h * DK_;
#pragma unroll
    for (int ni = 0; ni < 8; ni++) {
        const int c = ni * 8 + t * 2;
        float2 o0, o1;
        o0.x = O[ni][0] * ri0; o0.y = O[ni][1] * ri0;
        o1.x = O[ni][2] * ri1; o1.y = O[ni][3] * ri1;
        *(float2*)(C0 + c) = o0;
        *(float2*)(C1 + c) = o1;
    }
}

// ---------------------------------------------------------------------------
// Launch
// ---------------------------------------------------------------------------
extern "C" void kernel_launch(void* const* d_in, const int* in_sizes, int n_in,
                              void* d_out, int out_size)
{
    const float* query = (const float*)d_in[0];
    const float* key   = (const float*)d_in[1];
    const float* value = (const float*)d_in[2];
    const int*   mask  = (const int*)d_in[3];
    const float* w_q = (const float*)d_in[4];
    const float* b_q = (const float*)d_in[5];
    const float* w_k = (const float*)d_in[6];
    const float* b_k = (const float*)d_in[7];
    const float* w_v = (const float*)d_in[8];
    const float* b_v = (const float*)d_in[9];
    const float* w_o = (const float*)d_in[10];
    const float* b_o = (const float*)d_in[11];

    float *gq, *gk, *gv, *gc;
    cudaGetSymbolAddress((void**)&gq, g_q);
    cudaGetSymbolAddress((void**)&gk, g_k);
    cudaGetSymbolAddress((void**)&gv, g_v);
    cudaGetSymbolAddress((void**)&gc, g_ctx);

    cudaFuncSetAttribute(flash_tc,
                         cudaFuncAttributeMaxDynamicSharedMemorySize,
                         FLASH_SMEM);

    const int M = B_ * S_;                        // 4096
    dim3 gproj(D_ / 128, M / 128);                // (8, 32) = 256 CTAs

    gemm_tc<<<gproj, 256, GEMM_SMEM>>>(query, w_q, b_q, gq, M, D_, D_);
    gemm_tc<<<gproj, 256, GEMM_SMEM>>>(key,   w_k, b_k, gk, M, D_, D_);
    gemm_tc<<<gproj, 256, GEMM_SMEM>>>(value, w_v, b_v, gv, M, D_, D_);

    dim3 gflash(S_ / 128, H_, B_);                // (16, 16, 2) = 512 CTAs
    flash_tc<<<gflash, 256, FLASH_SMEM>>>(gq, gk, gv, mask, gc);

    gemm_tc<<<gproj, 256, GEMM_SMEM>>>(gc, w_o, b_o, (float*)d_out, M, D_, D_);
}

// round 11
// speedup vs baseline: 2.0821x; 1.1368x over previous
#include <cuda_runtime.h>
#include <cuda_bf16.h>
#include <cstdint>

#define B_  2
#define S_  2048
#define D_  1024
#define H_  16
#define DK_ 64
#define NEGV -1.0e9f

// Scratch (allocation-free rule: __device__ globals)
__device__ float g_q[B_ * S_ * D_];
__device__ float g_k[B_ * S_ * D_];
__device__ float g_v[B_ * S_ * D_];
__device__ float g_ctx[B_ * S_ * D_];

// ===========================================================================
// Common helpers
// ===========================================================================
#define MMA16816(c, a, b) \
    asm volatile("mma.sync.aligned.m16n8k16.row.col.f32.bf16.bf16.f32 " \
        "{%0,%1,%2,%3}, {%4,%5,%6,%7}, {%8,%9}, {%0,%1,%2,%3};" \
        : "+f"((c)[0]), "+f"((c)[1]), "+f"((c)[2]), "+f"((c)[3]) \
        : "r"((a)[0]), "r"((a)[1]), "r"((a)[2]), "r"((a)[3]), \
          "r"((b)[0]), "r"((b)[1]))

__device__ __forceinline__ uint32_t pack2bf(__nv_bfloat16 a, __nv_bfloat16 b) {
    return (uint32_t)__bfloat16_as_ushort(a) |
           ((uint32_t)__bfloat16_as_ushort(b) << 16);
}

// Convert 16 fp32 (4 float4) -> 16 bf16 hi + 16 bf16 lo, store 2 uint4 each.
__device__ __forceinline__ void store_split16(
    const float4* v, char* hi, char* lo, uint32_t boff)
{
    uint32_t hw[8], lw[8];
#pragma unroll
    for (int q = 0; q < 4; q++) {
        float x[4] = {v[q].x, v[q].y, v[q].z, v[q].w};
#pragma unroll
        for (int p = 0; p < 2; p++) {
            float x0 = x[2 * p], x1 = x[2 * p + 1];
            __nv_bfloat16 h0 = __float2bfloat16_rn(x0);
            __nv_bfloat16 h1 = __float2bfloat16_rn(x1);
            __nv_bfloat16 l0 = __float2bfloat16_rn(x0 - __bfloat162float(h0));
            __nv_bfloat16 l1 = __float2bfloat16_rn(x1 - __bfloat162float(h1));
            hw[q * 2 + p] = pack2bf(h0, h1);
            lw[q * 2 + p] = pack2bf(l0, l1);
        }
    }
    *(uint4*)(hi + boff)      = make_uint4(hw[0], hw[1], hw[2], hw[3]);
    *(uint4*)(hi + boff + 16) = make_uint4(hw[4], hw[5], hw[6], hw[7]);
    *(uint4*)(lo + boff)      = make_uint4(lw[0], lw[1], lw[2], lw[3]);
    *(uint4*)(lo + boff + 16) = make_uint4(lw[4], lw[5], lw[6], lw[7]);
}

// ===========================================================================
// bf16 HMMA GEMM, 2 CTAs/SM (reg-capped 128; frag loads interleaved)
// ===========================================================================
#define GSTRIDE 80
#define OFF_AH 0
#define OFF_AL (128 * GSTRIDE)
#define OFF_BH (2 * 128 * GSTRIDE)
#define OFF_BL (3 * 128 * GSTRIDE)
#define GEMM_SMEM (4 * 128 * GSTRIDE)   // 40960 B

__global__ __launch_bounds__(256, 2) void gemm_tc(
    const float* __restrict__ A, const float* __restrict__ Bw,
    const float* __restrict__ bias, float* __restrict__ C,
    int M, int N, int K)
{
    extern __shared__ char smc[];
    char* AH = smc + OFF_AH;
    char* AL = smc + OFF_AL;
    char* BH = smc + OFF_BH;
    char* BL = smc + OFF_BL;

    const int tid = threadIdx.x;
    const int wid = tid >> 5, lane = tid & 31;
    const int g = lane >> 2, t = lane & 3;
    const int warp_m = wid & 3;
    const int warp_n = wid >> 2;
    const int m0 = blockIdx.y * 128;
    const int n0 = blockIdx.x * 128;

    const int r = tid >> 1, h = tid & 1;
    const float* gA = A + (size_t)(m0 + r) * K + h * 16;
    const float* gB = Bw + (size_t)(n0 + r) * K + h * 16;
    const uint32_t boff = (uint32_t)r * GSTRIDE + h * 32;

    float acc[2][8][4];
#pragma unroll
    for (int mi = 0; mi < 2; mi++)
#pragma unroll
        for (int ni = 0; ni < 8; ni++)
#pragma unroll
            for (int c = 0; c < 4; c++) acc[mi][ni][c] = 0.f;

    float4 vA[4], vB[4];
#pragma unroll
    for (int q = 0; q < 4; q++) {
        vA[q] = *(const float4*)(gA + q * 4);
        vB[q] = *(const float4*)(gB + q * 4);
    }

    const int nchunks = K / 32;
    for (int ck = 0; ck < nchunks; ck++) {
        __syncthreads();
        store_split16(vA, AH, AL, boff);
        store_split16(vB, BH, BL, boff);
        __syncthreads();

        if (ck + 1 < nchunks) {
            const float* pa = gA + (ck + 1) * 32;
            const float* pb = gB + (ck + 1) * 32;
#pragma unroll
            for (int q = 0; q < 4; q++) {
                vA[q] = *(const float4*)(pa + q * 4);
                vB[q] = *(const float4*)(pb + q * 4);
            }
        }

#pragma unroll
        for (int ks = 0; ks < 2; ks++) {
            const uint32_t ko = (uint32_t)(ks * 16 + t * 2) * 2;
#pragma unroll
            for (int mi = 0; mi < 2; mi++) {
                uint32_t ah[4], alr[4];
                {
                    const uint32_t o = (uint32_t)(warp_m * 32 + mi * 16 + g) * GSTRIDE + ko;
                    ah[0]  = *(const uint32_t*)(AH + o);
                    ah[1]  = *(const uint32_t*)(AH + o + 8 * GSTRIDE);
                    ah[2]  = *(const uint32_t*)(AH + o + 16);
                    ah[3]  = *(const uint32_t*)(AH + o + 8 * GSTRIDE + 16);
                    alr[0] = *(const uint32_t*)(AL + o);
                    alr[1] = *(const uint32_t*)(AL + o + 8 * GSTRIDE);
                    alr[2] = *(const uint32_t*)(AL + o + 16);
                    alr[3] = *(const uint32_t*)(AL + o + 8 * GSTRIDE + 16);
                }
#pragma unroll
                for (int ni = 0; ni < 8; ni++) {
                    uint32_t bh[2], bl[2];
                    const uint32_t o = (uint32_t)(warp_n * 64 + ni * 8 + g) * GSTRIDE + ko;
                    bh[0] = *(const uint32_t*)(BH + o);
                    bh[1] = *(const uint32_t*)(BH + o + 16);
                    bl[0] = *(const uint32_t*)(BL + o);
                    bl[1] = *(const uint32_t*)(BL + o + 16);
                    MMA16816(acc[mi][ni], ah, bh);
                    MMA16816(acc[mi][ni], ah, bl);
                    MMA16816(acc[mi][ni], alr, bh);
                }
            }
        }
    }

#pragma unroll
    for (int mi = 0; mi < 2; mi++) {
        const int row0 = m0 + warp_m * 32 + mi * 16 + g;
#pragma unroll
        for (int ni = 0; ni < 8; ni++) {
            const int col = n0 + warp_n * 64 + ni * 8 + t * 2;
            float2 bi = *(const float2*)&bias[col];
            float2 o0, o1;
            o0.x = acc[mi][ni][0] + bi.x;
            o0.y = acc[mi][ni][1] + bi.y;
            o1.x = acc[mi][ni][2] + bi.x;
            o1.y = acc[mi][ni][3] + bi.y;
            *(float2*)&C[(size_t)row0 * N + col] = o0;
            *(float2*)&C[(size_t)(row0 + 8) * N + col] = o1;
        }
    }
}

// ===========================================================================
// Tensor-core flash attention, 2 CTAs/SM.
// CTA = 128 q-rows x one (b,h). 8 warps, each owns 16 full q-rows.
// qh fragments hoisted; ql fragments re-loaded per key-tile (reg diet).
// ===========================================================================
#define FSTB 144                       // bytes per smem row (72 bf16)
#define FQ_H 0
#define FQ_L (128 * FSTB)              // 18432
#define FK_H (2 * 128 * FSTB)          // 36864
#define FK_L (FK_H + 64 * FSTB)        // 46080
#define FV_H (FK_L + 64 * FSTB)        // 55296
#define FV_L (FV_H + 64 * FSTB)        // 64512
#define FLASH_SMEM (FV_L + 64 * FSTB)  // 73728

__global__ __launch_bounds__(256, 2) void flash_tc(
    const float* __restrict__ Q, const float* __restrict__ K,
    const float* __restrict__ V, const int* __restrict__ mask,
    float* __restrict__ ctx)
{
    extern __shared__ char smf[];
    const int tid = threadIdx.x;
    const int wid = tid >> 5, lane = tid & 31;
    const int g = lane >> 2, t = lane & 3;
    const int b = blockIdx.z, h = blockIdx.y;
    const int q0 = blockIdx.x * 128;

    const float* Qb = Q + ((size_t)b * S_ + q0) * D_ + h * DK_;
    const float* Kb = K + (size_t)b * S_ * D_ + h * DK_;
    const float* Vb = V + (size_t)b * S_ * D_ + h * DK_;
    const int*   Mb = mask + (size_t)b * S_ * S_;

    // ---- Stage Q once: scale 0.125, split hi/lo ----
    {
        const int r = tid >> 1, hf = tid & 1;
        const float* src = Qb + (size_t)r * D_ + hf * 32;
#pragma unroll
        for (int seg = 0; seg < 2; seg++) {
            float4 v[4];
#pragma unroll
            for (int j = 0; j < 4; j++) {
                float4 x = *(const float4*)(src + seg * 16 + j * 4);
                x.x *= 0.125f; x.y *= 0.125f; x.z *= 0.125f; x.w *= 0.125f;
                v[j] = x;
            }
            store_split16(v, smf + FQ_H, smf + FQ_L,
                          (uint32_t)r * FSTB + hf * 64 + seg * 32);
        }
    }
    __syncthreads();

    // ---- Hoist Q hi fragments only (reg diet for 2 CTAs/SM) ----
    const uint32_t qrowb = (uint32_t)(wid * 16 + g) * FSTB + (uint32_t)t * 4;
    uint32_t qh[4][4];
#pragma unroll
    for (int ks = 0; ks < 4; ks++) {
        const uint32_t o = qrowb + ks * 32;
        qh[ks][0] = *(const uint32_t*)(smf + FQ_H + o);
        qh[ks][1] = *(const uint32_t*)(smf + FQ_H + o + 8 * FSTB);
        qh[ks][2] = *(const uint32_t*)(smf + FQ_H + o + 16);
        qh[ks][3] = *(const uint32_t*)(smf + FQ_H + o + 8 * FSTB + 16);
    }

    float O[8][4];
#pragma unroll
    for (int ni = 0; ni < 8; ni++)
#pragma unroll
        for (int c = 0; c < 4; c++) O[ni][c] = 0.f;

    float m0r = -3.0e38f, m1r = -3.0e38f;
    float l0r = 0.f, l1r = 0.f;

    const int r0g = q0 + wid * 16 + g;
    const int r1g = r0g + 8;

    const int kr = tid >> 2;
    const int cs = (tid & 3) * 16;

    for (int kt = 0; kt < S_; kt += 64) {
        __syncthreads();
        // ---- Stage K (natural) and V (transposed), both split ----
        {
            const float* srcK = Kb + (size_t)(kt + kr) * D_ + cs;
            float4 v[4];
#pragma unroll
            for (int j = 0; j < 4; j++) v[j] = *(const float4*)(srcK + j * 4);
            store_split16(v, smf + FK_H, smf + FK_L,
                          (uint32_t)kr * FSTB + cs * 2);

            const float* srcV = Vb + (size_t)(kt + kr) * D_ + cs;
#pragma unroll
            for (int j = 0; j < 4; j++) {
                float4 x = *(const float4*)(srcV + j * 4);
                float vv[4] = {x.x, x.y, x.z, x.w};
#pragma unroll
                for (int e = 0; e < 4; e++) {
                    __nv_bfloat16 hb = __float2bfloat16_rn(vv[e]);
                    __nv_bfloat16 lb =
                        __float2bfloat16_rn(vv[e] - __bfloat162float(hb));
                    const uint32_t o = (uint32_t)(cs + j * 4 + e) * FSTB + kr * 2;
                    *(__nv_bfloat16*)(smf + FV_H + o) = hb;
                    *(__nv_bfloat16*)(smf + FV_L + o) = lb;
                }
            }
        }
        __syncthreads();

        // ---- S = (Q*0.125) @ K^T : ks-outer so ql loads 4 regs per ks ----
        float s[8][4];
#pragma unroll
        for (int ni = 0; ni < 8; ni++)
#pragma unroll
            for (int c = 0; c < 4; c++) s[ni][c] = 0.f;

#pragma unroll
        for (int ks = 0; ks < 4; ks++) {
            uint32_t ql[4];
            {
                const uint32_t o = qrowb + ks * 32;
                ql[0] = *(const uint32_t*)(smf + FQ_L + o);
                ql[1] = *(const uint32_t*)(smf + FQ_L + o + 8 * FSTB);
                ql[2] = *(const uint32_t*)(smf + FQ_L + o + 16);
                ql[3] = *(const uint32_t*)(smf + FQ_L + o + 8 * FSTB + 16);
            }
#pragma unroll
            for (int ni = 0; ni < 8; ni++) {
                const uint32_t o = (uint32_t)(ni * 8 + g) * FSTB +
                                   (uint32_t)t * 4 + ks * 32;
                uint32_t kbh[2], kbl[2];
                kbh[0] = *(const uint32_t*)(smf + FK_H + o);
                kbh[1] = *(const uint32_t*)(smf + FK_H + o + 16);
                kbl[0] = *(const uint32_t*)(smf + FK_L + o);
                kbl[1] = *(const uint32_t*)(smf + FK_L + o + 16);
                MMA16816(s[ni], qh[ks], kbh);
                MMA16816(s[ni], qh[ks], kbl);
                MMA16816(s[ni], ql, kbh);
            }
        }

        // ---- Mask ----
#pragma unroll
        for (int ni = 0; ni < 8; ni++) {
            const int c = kt + ni * 8 + t * 2;
            int2 mk0 = *(const int2*)(Mb + (size_t)r0g * S_ + c);
            int2 mk1 = *(const int2*)(Mb + (size_t)r1g * S_ + c);
            if (!mk0.x) s[ni][0] = NEGV;
            if (!mk0.y) s[ni][1] = NEGV;
            if (!mk1.x) s[ni][2] = NEGV;
            if (!mk1.y) s[ni][3] = NEGV;
        }

        // ---- Online softmax (within t-quad) ----
        float mx0 = s[0][0], mx1 = s[0][2];
#pragma unroll
        for (int ni = 0; ni < 8; ni++) {
            mx0 = fmaxf(mx0, fmaxf(s[ni][0], s[ni][1]));
            mx1 = fmaxf(mx1, fmaxf(s[ni][2], s[ni][3]));
        }
        mx0 = fmaxf(mx0, __shfl_xor_sync(0xffffffffu, mx0, 1));
        mx0 = fmaxf(mx0, __shfl_xor_sync(0xffffffffu, mx0, 2));
        mx1 = fmaxf(mx1, __shfl_xor_sync(0xffffffffu, mx1, 1));
        mx1 = fmaxf(mx1, __shfl_xor_sync(0xffffffffu, mx1, 2));

        const float mn0 = fmaxf(m0r, mx0);
        const float mn1 = fmaxf(m1r, mx1);
        const float a0 = __expf(m0r - mn0);
        const float a1 = __expf(m1r - mn1);
        m0r = mn0; m1r = mn1;

        float sum0 = 0.f, sum1 = 0.f;
#pragma unroll
        for (int ni = 0; ni < 8; ni++) {
            s[ni][0] = __expf(s[ni][0] - mn0);
            s[ni][1] = __expf(s[ni][1] - mn0);
            s[ni][2] = __expf(s[ni][2] - mn1);
            s[ni][3] = __expf(s[ni][3] - mn1);
            sum0 += s[ni][0] + s[ni][1];
            sum1 += s[ni][2] + s[ni][3];
        }
        sum0 += __shfl_xor_sync(0xffffffffu, sum0, 1);
        sum0 += __shfl_xor_sync(0xffffffffu, sum0, 2);
        sum1 += __shfl_xor_sync(0xffffffffu, sum1, 1);
        sum1 += __shfl_xor_sync(0xffffffffu, sum1, 2);
        l0r = l0r * a0 + sum0;
        l1r = l1r * a1 + sum1;

#pragma unroll
        for (int ni = 0; ni < 8; ni++) {
            O[ni][0] *= a0; O[ni][1] *= a0;
            O[ni][2] *= a1; O[ni][3] *= a1;
        }

        // ---- PV: O += P @ V (P from regs, split) ----
#pragma unroll
        for (int ksp = 0; ksp < 4; ksp++) {
            uint32_t pah[4], pal[4];
#pragma unroll
            for (int hf = 0; hf < 2; hf++) {
                const float* p = s[2 * ksp + hf];
                __nv_bfloat16 h0 = __float2bfloat16_rn(p[0]);
                __nv_bfloat16 h1 = __float2bfloat16_rn(p[1]);
                __nv_bfloat16 h2 = __float2bfloat16_rn(p[2]);
                __nv_bfloat16 h3 = __float2bfloat16_rn(p[3]);
                __nv_bfloat16 l0 = __float2bfloat16_rn(p[0] - __bfloat162float(h0));
                __nv_bfloat16 l1 = __float2bfloat16_rn(p[1] - __bfloat162float(h1));
                __nv_bfloat16 l2 = __float2bfloat16_rn(p[2] - __bfloat162float(h2));
                __nv_bfloat16 l3 = __float2bfloat16_rn(p[3] - __bfloat162float(h3));
                pah[hf * 2 + 0] = pack2bf(h0, h1);
                pah[hf * 2 + 1] = pack2bf(h2, h3);
                pal[hf * 2 + 0] = pack2bf(l0, l1);
                pal[hf * 2 + 1] = pack2bf(l2, l3);
            }
#pragma unroll
            for (int ni = 0; ni < 8; ni++) {
                const uint32_t o = (uint32_t)(ni * 8 + g) * FSTB +
                                   (uint32_t)(ksp * 16 + t * 2) * 2;
                uint32_t vbh[2], vbl[2];
                vbh[0] = *(const uint32_t*)(smf + FV_H + o);
                vbh[1] = *(const uint32_t*)(smf + FV_H + o + 16);
                vbl[0] = *(const uint32_t*)(smf + FV_L + o);
                vbl[1] = *(const uint32_t*)(smf + FV_L + o + 16);
                MMA16816(O[ni], pah, vbh);
                MMA16816(O[ni], pah, vbl);
                MMA16816(O[ni], pal, vbh);
            }
        }
    }

    // ---- Final normalize + store ----
    const float ri0 = 1.f / l0r;
    const float ri1 = 1.f / l1r;
    float* C0 = ctx + ((size_t)b * S_ + r0g) * D_ + h * DK_;
    float* C1 = ctx + ((size_t)b * S_ + r1g) * D_ + h * DK_;
#pragma unroll
    for (int ni = 0; ni < 8; ni++) {
        const int c = ni * 8 + t * 2;
        float2 o0, o1;
        o0.x = O[ni][0] * ri0; o0.y = O[ni][1] * ri0;
        o1.x = O[ni][2] * ri1; o1.y = O[ni][3] * ri1;
        *(float2*)(C0 + c) = o0;
        *(float2*)(C1 + c) = o1;
    }
}

// ---------------------------------------------------------------------------
// Launch
// ---------------------------------------------------------------------------
extern "C" void kernel_launch(void* const* d_in, const int* in_sizes, int n_in,
                              void* d_out, int out_size)
{
    const float* query = (const float*)d_in[0];
    const float* key   = (const float*)d_in[1];
    const float* value = (const float*)d_in[2];
    const int*   mask  = (const int*)d_in[3];
    const float* w_q = (const float*)d_in[4];
    const float* b_q = (const float*)d_in[5];
    const float* w_k = (const float*)d_in[6];
    const float* b_k = (const float*)d_in[7];
    const float* w_v = (const float*)d_in[8];
    const float* b_v = (const float*)d_in[9];
    const float* w_o = (const float*)d_in[10];
    const float* b_o = (const float*)d_in[11];

    float *gq, *gk, *gv, *gc;
    cudaGetSymbolAddress((void**)&gq, g_q);
    cudaGetSymbolAddress((void**)&gk, g_k);
    cudaGetSymbolAddress((void**)&gv, g_v);
    cudaGetSymbolAddress((void**)&gc, g_ctx);

    cudaFuncSetAttribute(flash_tc,
                         cudaFuncAttributeMaxDynamicSharedMemorySize,
                         FLASH_SMEM);

    const int M = B_ * S_;                        // 4096
    dim3 gproj(D_ / 128, M / 128);                // (8, 32) = 256 CTAs

    gemm_tc<<<gproj, 256, GEMM_SMEM>>>(query, w_q, b_q, gq, M, D_, D_);
    gemm_tc<<<gproj, 256, GEMM_SMEM>>>(key,   w_k, b_k, gk, M, D_, D_);
    gemm_tc<<<gproj, 256, GEMM_SMEM>>>(value, w_v, b_v, gv, M, D_, D_);

    dim3 gflash(S_ / 128, H_, B_);                // (16, 16, 2) = 512 CTAs
    flash_tc<<<gflash, 256, FLASH_SMEM>>>(gq, gk, gv, mask, gc);

    gemm_tc<<<gproj, 256, GEMM_SMEM>>>(gc, w_o, b_o, (float*)d_out, M, D_, D_);
}

// round 12
// speedup vs baseline: 2.3924x; 1.1490x over previous
#include <cuda_runtime.h>
#include <cuda_bf16.h>
#include <cstdint>

#define B_  2
#define S_  2048
#define D_  1024
#define H_  16
#define DK_ 64
#define NEGV -1.0e9f

// Scratch (allocation-free rule: __device__ globals)
__device__ float g_q[B_ * S_ * D_];
__device__ float g_k[B_ * S_ * D_];
__device__ float g_v[B_ * S_ * D_];
__device__ float g_ctx[B_ * S_ * D_];

// ===========================================================================
// Common helpers
// ===========================================================================
#define MMA16816(c, a, b) \
    asm volatile("mma.sync.aligned.m16n8k16.row.col.f32.bf16.bf16.f32 " \
        "{%0,%1,%2,%3}, {%4,%5,%6,%7}, {%8,%9}, {%0,%1,%2,%3};" \
        : "+f"((c)[0]), "+f"((c)[1]), "+f"((c)[2]), "+f"((c)[3]) \
        : "r"((a)[0]), "r"((a)[1]), "r"((a)[2]), "r"((a)[3]), \
          "r"((b)[0]), "r"((b)[1]))

#define LDSM_X4(d, addr) \
    asm volatile("ldmatrix.sync.aligned.m8n8.x4.shared.b16 {%0,%1,%2,%3}, [%4];" \
        : "=r"((d)[0]), "=r"((d)[1]), "=r"((d)[2]), "=r"((d)[3]) : "r"(addr))

#define LDSM_X2(d, addr) \
    asm volatile("ldmatrix.sync.aligned.m8n8.x2.shared.b16 {%0,%1}, [%2];" \
        : "=r"((d)[0]), "=r"((d)[1]) : "r"(addr))

#define LDSM_X2T(d, addr) \
    asm volatile("ldmatrix.sync.aligned.m8n8.x2.trans.shared.b16 {%0,%1}, [%2];" \
        : "=r"((d)[0]), "=r"((d)[1]) : "r"(addr))

__device__ __forceinline__ uint32_t smem_u32(const void* p) {
    uint32_t a;
    asm("{ .reg .u64 t; cvta.to.shared.u64 t, %1; cvt.u32.u64 %0, t; }"
        : "=r"(a) : "l"(p));
    return a;
}

__device__ __forceinline__ uint32_t pack2bf(__nv_bfloat16 a, __nv_bfloat16 b) {
    return (uint32_t)__bfloat16_as_ushort(a) |
           ((uint32_t)__bfloat16_as_ushort(b) << 16);
}

// Convert 16 fp32 (4 float4) -> 16 bf16 hi + 16 bf16 lo via cvt.rn.bf16x2.
__device__ __forceinline__ void store_split16(
    const float4* v, char* hi, char* lo, uint32_t boff)
{
    uint32_t hw[8], lw[8];
#pragma unroll
    for (int q = 0; q < 4; q++) {
        __nv_bfloat162 h0 = __floats2bfloat162_rn(v[q].x, v[q].y);
        __nv_bfloat162 h1 = __floats2bfloat162_rn(v[q].z, v[q].w);
        float2 f0 = __bfloat1622float2(h0);
        float2 f1 = __bfloat1622float2(h1);
        __nv_bfloat162 l0 = __floats2bfloat162_rn(v[q].x - f0.x, v[q].y - f0.y);
        __nv_bfloat162 l1 = __floats2bfloat162_rn(v[q].z - f1.x, v[q].w - f1.y);
        hw[q * 2]     = *(const uint32_t*)&h0;
        hw[q * 2 + 1] = *(const uint32_t*)&h1;
        lw[q * 2]     = *(const uint32_t*)&l0;
        lw[q * 2 + 1] = *(const uint32_t*)&l1;
    }
    *(uint4*)(hi + boff)      = make_uint4(hw[0], hw[1], hw[2], hw[3]);
    *(uint4*)(hi + boff + 16) = make_uint4(hw[4], hw[5], hw[6], hw[7]);
    *(uint4*)(lo + boff)      = make_uint4(lw[0], lw[1], lw[2], lw[3]);
    *(uint4*)(lo + boff + 16) = make_uint4(lw[4], lw[5], lw[6], lw[7]);
}

// ===========================================================================
// bf16 HMMA GEMM, 2 CTAs/SM, ldmatrix fragment loads.
// ===========================================================================
#define GSTRIDE 80
#define OFF_AH 0
#define OFF_AL (128 * GSTRIDE)
#define OFF_BH (2 * 128 * GSTRIDE)
#define OFF_BL (3 * 128 * GSTRIDE)
#define GEMM_SMEM (4 * 128 * GSTRIDE)   // 40960 B

__global__ __launch_bounds__(256, 2) void gemm_tc(
    const float* __restrict__ A, const float* __restrict__ Bw,
    const float* __restrict__ bias, float* __restrict__ C,
    int M, int N, int K)
{
    extern __shared__ char smc[];
    char* AH = smc + OFF_AH;
    char* AL = smc + OFF_AL;
    char* BH = smc + OFF_BH;
    char* BL = smc + OFF_BL;
    const uint32_t sbG = smem_u32(smc);

    const int tid = threadIdx.x;
    const int wid = tid >> 5, lane = tid & 31;
    const int g = lane >> 2, t = lane & 3;
    const int warp_m = wid & 3;
    const int warp_n = wid >> 2;
    const int m0 = blockIdx.y * 128;
    const int n0 = blockIdx.x * 128;

    // ldmatrix per-lane base addresses
    const int l7 = lane & 7;
    const int lh = (lane >> 3) & 1;
    const int lq = lane >> 4;
    const uint32_t aBase = sbG +
        (uint32_t)(warp_m * 32 + l7 + lh * 8) * GSTRIDE + (uint32_t)lq * 16;
    const uint32_t bBase = sbG +
        (uint32_t)(warp_n * 64 + l7) * GSTRIDE + (uint32_t)lh * 16;

    const int r = tid >> 1, h = tid & 1;
    const float* gA = A + (size_t)(m0 + r) * K + h * 16;
    const float* gB = Bw + (size_t)(n0 + r) * K + h * 16;
    const uint32_t boff = (uint32_t)r * GSTRIDE + h * 32;

    float acc[2][8][4];
#pragma unroll
    for (int mi = 0; mi < 2; mi++)
#pragma unroll
        for (int ni = 0; ni < 8; ni++)
#pragma unroll
            for (int c = 0; c < 4; c++) acc[mi][ni][c] = 0.f;

    float4 vA[4], vB[4];
#pragma unroll
    for (int q = 0; q < 4; q++) {
        vA[q] = *(const float4*)(gA + q * 4);
        vB[q] = *(const float4*)(gB + q * 4);
    }

    const int nchunks = K / 32;
    for (int ck = 0; ck < nchunks; ck++) {
        __syncthreads();
        store_split16(vA, AH, AL, boff);
        store_split16(vB, BH, BL, boff);
        __syncthreads();

        if (ck + 1 < nchunks) {
            const float* pa = gA + (ck + 1) * 32;
            const float* pb = gB + (ck + 1) * 32;
#pragma unroll
            for (int q = 0; q < 4; q++) {
                vA[q] = *(const float4*)(pa + q * 4);
                vB[q] = *(const float4*)(pb + q * 4);
            }
        }

#pragma unroll
        for (int ks = 0; ks < 2; ks++) {
#pragma unroll
            for (int mi = 0; mi < 2; mi++) {
                uint32_t ah[4], al[4];
                LDSM_X4(ah, aBase + OFF_AH + mi * (16 * GSTRIDE) + ks * 32);
                LDSM_X4(al, aBase + OFF_AL + mi * (16 * GSTRIDE) + ks * 32);
#pragma unroll
                for (int ni = 0; ni < 8; ni++) {
                    uint32_t bh[2], bl[2];
                    LDSM_X2(bh, bBase + OFF_BH + ni * (8 * GSTRIDE) + ks * 32);
                    LDSM_X2(bl, bBase + OFF_BL + ni * (8 * GSTRIDE) + ks * 32);
                    MMA16816(acc[mi][ni], ah, bh);
                    MMA16816(acc[mi][ni], ah, bl);
                    MMA16816(acc[mi][ni], al, bh);
                }
            }
        }
    }

#pragma unroll
    for (int mi = 0; mi < 2; mi++) {
        const int row0 = m0 + warp_m * 32 + mi * 16 + g;
#pragma unroll
        for (int ni = 0; ni < 8; ni++) {
            const int col = n0 + warp_n * 64 + ni * 8 + t * 2;
            float2 bi = *(const float2*)&bias[col];
            float2 o0, o1;
            o0.x = acc[mi][ni][0] + bi.x;
            o0.y = acc[mi][ni][1] + bi.y;
            o1.x = acc[mi][ni][2] + bi.x;
            o1.y = acc[mi][ni][3] + bi.y;
            *(float2*)&C[(size_t)row0 * N + col] = o0;
            *(float2*)&C[(size_t)(row0 + 8) * N + col] = o1;
        }
    }
}

// ===========================================================================
// Tensor-core flash attention, 2 CTAs/SM, ldmatrix fragment loads.
// V staged NATURAL [key][dk]; transpose happens in ldmatrix.x2.trans.
// ===========================================================================
#define FSTB 144                       // bytes per smem row (72 bf16)
#define FQ_H 0
#define FQ_L (128 * FSTB)              // 18432
#define FK_H (2 * 128 * FSTB)          // 36864
#define FK_L (FK_H + 64 * FSTB)        // 46080
#define FV_H (FK_L + 64 * FSTB)        // 55296
#define FV_L (FV_H + 64 * FSTB)        // 64512
#define FLASH_SMEM (FV_L + 64 * FSTB)  // 73728

__global__ __launch_bounds__(256, 2) void flash_tc(
    const float* __restrict__ Q, const float* __restrict__ K,
    const float* __restrict__ V, const int* __restrict__ mask,
    float* __restrict__ ctx)
{
    extern __shared__ char smf[];
    const uint32_t sb = smem_u32(smf);
    const int tid = threadIdx.x;
    const int wid = tid >> 5, lane = tid & 31;
    const int g = lane >> 2, t = lane & 3;
    const int b = blockIdx.z, h = blockIdx.y;
    const int q0 = blockIdx.x * 128;

    const float* Qb = Q + ((size_t)b * S_ + q0) * D_ + h * DK_;
    const float* Kb = K + (size_t)b * S_ * D_ + h * DK_;
    const float* Vb = V + (size_t)b * S_ * D_ + h * DK_;
    const int*   Mb = mask + (size_t)b * S_ * S_;

    // ldmatrix per-lane base addresses
    const int l7 = lane & 7;
    const int lh = (lane >> 3) & 1;
    const int lq = lane >> 4;
    const uint32_t qBase = sb +
        (uint32_t)(wid * 16 + l7 + lh * 8) * FSTB + (uint32_t)lq * 16;
    const uint32_t kBase = sb + (uint32_t)l7 * FSTB + (uint32_t)lh * 16;
    const uint32_t vBase = sb + (uint32_t)(l7 + lh * 8) * FSTB;

    // ---- Stage Q once: scale 0.125, split hi/lo ----
    {
        const int r = tid >> 1, hf = tid & 1;
        const float* src = Qb + (size_t)r * D_ + hf * 32;
#pragma unroll
        for (int seg = 0; seg < 2; seg++) {
            float4 v[4];
#pragma unroll
            for (int j = 0; j < 4; j++) {
                float4 x = *(const float4*)(src + seg * 16 + j * 4);
                x.x *= 0.125f; x.y *= 0.125f; x.z *= 0.125f; x.w *= 0.125f;
                v[j] = x;
            }
            store_split16(v, smf + FQ_H, smf + FQ_L,
                          (uint32_t)r * FSTB + hf * 64 + seg * 32);
        }
    }

    float O[8][4];
#pragma unroll
    for (int ni = 0; ni < 8; ni++)
#pragma unroll
        for (int c = 0; c < 4; c++) O[ni][c] = 0.f;

    float m0r = -3.0e38f, m1r = -3.0e38f;
    float l0r = 0.f, l1r = 0.f;

    const int r0g = q0 + wid * 16 + g;
    const int r1g = r0g + 8;

    const int kr = tid >> 2;
    const int cs = (tid & 3) * 16;

    for (int kt = 0; kt < S_; kt += 64) {
        __syncthreads();
        // ---- Stage K and V (both natural [row][dk], split hi/lo) ----
        {
            const float* srcK = Kb + (size_t)(kt + kr) * D_ + cs;
            float4 v[4];
#pragma unroll
            for (int j = 0; j < 4; j++) v[j] = *(const float4*)(srcK + j * 4);
            store_split16(v, smf + FK_H, smf + FK_L,
                          (uint32_t)kr * FSTB + cs * 2);

            const float* srcV = Vb + (size_t)(kt + kr) * D_ + cs;
#pragma unroll
            for (int j = 0; j < 4; j++) v[j] = *(const float4*)(srcV + j * 4);
            store_split16(v, smf + FV_H, smf + FV_L,
                          (uint32_t)kr * FSTB + cs * 2);
        }
        __syncthreads();

        // ---- S = (Q*0.125) @ K^T : 3-term split, ldmatrix frags ----
        float s[8][4];
#pragma unroll
        for (int ni = 0; ni < 8; ni++)
#pragma unroll
            for (int c = 0; c < 4; c++) s[ni][c] = 0.f;

#pragma unroll
        for (int ks = 0; ks < 4; ks++) {
            uint32_t qh[4], ql[4];
            LDSM_X4(qh, qBase + FQ_H + ks * 32);
            LDSM_X4(ql, qBase + FQ_L + ks * 32);
#pragma unroll
            for (int ni = 0; ni < 8; ni++) {
                uint32_t kh[2], kl[2];
                LDSM_X2(kh, kBase + FK_H + ni * (8 * FSTB) + ks * 32);
                LDSM_X2(kl, kBase + FK_L + ni * (8 * FSTB) + ks * 32);
                MMA16816(s[ni], qh, kh);
                MMA16816(s[ni], qh, kl);
                MMA16816(s[ni], ql, kh);
            }
        }

        // ---- Mask ----
#pragma unroll
        for (int ni = 0; ni < 8; ni++) {
            const int c = kt + ni * 8 + t * 2;
            int2 mk0 = *(const int2*)(Mb + (size_t)r0g * S_ + c);
            int2 mk1 = *(const int2*)(Mb + (size_t)r1g * S_ + c);
            if (!mk0.x) s[ni][0] = NEGV;
            if (!mk0.y) s[ni][1] = NEGV;
            if (!mk1.x) s[ni][2] = NEGV;
            if (!mk1.y) s[ni][3] = NEGV;
        }

        // ---- Online softmax (within t-quad) ----
        float mx0 = s[0][0], mx1 = s[0][2];
#pragma unroll
        for (int ni = 0; ni < 8; ni++) {
            mx0 = fmaxf(mx0, fmaxf(s[ni][0], s[ni][1]));
            mx1 = fmaxf(mx1, fmaxf(s[ni][2], s[ni][3]));
        }
        mx0 = fmaxf(mx0, __shfl_xor_sync(0xffffffffu, mx0, 1));
        mx0 = fmaxf(mx0, __shfl_xor_sync(0xffffffffu, mx0, 2));
        mx1 = fmaxf(mx1, __shfl_xor_sync(0xffffffffu, mx1, 1));
        mx1 = fmaxf(mx1, __shfl_xor_sync(0xffffffffu, mx1, 2));

        const float mn0 = fmaxf(m0r, mx0);
        const float mn1 = fmaxf(m1r, mx1);
        const float a0 = __expf(m0r - mn0);
        const float a1 = __expf(m1r - mn1);
        m0r = mn0; m1r = mn1;

        float sum0 = 0.f, sum1 = 0.f;
#pragma unroll
        for (int ni = 0; ni < 8; ni++) {
            s[ni][0] = __expf(s[ni][0] - mn0);
            s[ni][1] = __expf(s[ni][1] - mn0);
            s[ni][2] = __expf(s[ni][2] - mn1);
            s[ni][3] = __expf(s[ni][3] - mn1);
            sum0 += s[ni][0] + s[ni][1];
            sum1 += s[ni][2] + s[ni][3];
        }
        sum0 += __shfl_xor_sync(0xffffffffu, sum0, 1);
        sum0 += __shfl_xor_sync(0xffffffffu, sum0, 2);
        sum1 += __shfl_xor_sync(0xffffffffu, sum1, 1);
        sum1 += __shfl_xor_sync(0xffffffffu, sum1, 2);
        l0r = l0r * a0 + sum0;
        l1r = l1r * a1 + sum1;

#pragma unroll
        for (int ni = 0; ni < 8; ni++) {
            O[ni][0] *= a0; O[ni][1] *= a0;
            O[ni][2] *= a1; O[ni][3] *= a1;
        }

        // ---- PV: O += P @ V (P from regs; V frags via ldmatrix.trans) ----
#pragma unroll
        for (int ksp = 0; ksp < 4; ksp++) {
            uint32_t pah[4], pal[4];
#pragma unroll
            for (int hf = 0; hf < 2; hf++) {
                const float* p = s[2 * ksp + hf];
                __nv_bfloat162 h01 = __floats2bfloat162_rn(p[0], p[1]);
                __nv_bfloat162 h23 = __floats2bfloat162_rn(p[2], p[3]);
                float2 f01 = __bfloat1622float2(h01);
                float2 f23 = __bfloat1622float2(h23);
                __nv_bfloat162 l01 =
                    __floats2bfloat162_rn(p[0] - f01.x, p[1] - f01.y);
                __nv_bfloat162 l23 =
                    __floats2bfloat162_rn(p[2] - f23.x, p[3] - f23.y);
                pah[hf * 2 + 0] = *(const uint32_t*)&h01;
                pah[hf * 2 + 1] = *(const uint32_t*)&h23;
                pal[hf * 2 + 0] = *(const uint32_t*)&l01;
                pal[hf * 2 + 1] = *(const uint32_t*)&l23;
            }
#pragma unroll
            for (int ni = 0; ni < 8; ni++) {
                uint32_t vh[2], vl[2];
                LDSM_X2T(vh, vBase + FV_H + ksp * (16 * FSTB) + ni * 16);
                LDSM_X2T(vl, vBase + FV_L + ksp * (16 * FSTB) + ni * 16);
                MMA16816(O[ni], pah, vh);
                MMA16816(O[ni], pah, vl);
                MMA16816(O[ni], pal, vh);
            }
        }
    }

    // ---- Final normalize + store ----
    const float ri0 = 1.f / l0r;
    const float ri1 = 1.f / l1r;
    float* C0 = ctx + ((size_t)b * S_ + r0g) * D_ + h * DK_;
    float* C1 = ctx + ((size_t)b * S_ + r1g) * D_ + h * DK_;
#pragma unroll
    for (int ni = 0; ni < 8; ni++) {
        const int c = ni * 8 + t * 2;
        float2 o0, o1;
        o0.x = O[ni][0] * ri0; o0.y = O[ni][1] * ri0;
        o1.x = O[ni][2] * ri1; o1.y = O[ni][3] * ri1;
        *(float2*)(C0 + c) = o0;
        *(float2*)(C1 + c) = o1;
    }
}

// ---------------------------------------------------------------------------
// Launch
// ---------------------------------------------------------------------------
extern "C" void kernel_launch(void* const* d_in, const int* in_sizes, int n_in,
                              void* d_out, int out_size)
{
    const float* query = (const float*)d_in[0];
    const float* key   = (const float*)d_in[1];
    const float* value = (const float*)d_in[2];
    const int*   mask  = (const int*)d_in[3];
    const float* w_q = (const float*)d_in[4];
    const float* b_q = (const float*)d_in[5];
    const float* w_k = (const float*)d_in[6];
    const float* b_k = (const float*)d_in[7];
    const float* w_v = (const float*)d_in[8];
    const float* b_v = (const float*)d_in[9];
    const float* w_o = (const float*)d_in[10];
    const float* b_o = (const float*)d_in[11];

    float *gq, *gk, *gv, *gc;
    cudaGetSymbolAddress((void**)&gq, g_q);
    cudaGetSymbolAddress((void**)&gk, g_k);
    cudaGetSymbolAddress((void**)&gv, g_v);
    cudaGetSymbolAddress((void**)&gc, g_ctx);

    cudaFuncSetAttribute(flash_tc,
                         cudaFuncAttributeMaxDynamicSharedMemorySize,
                         FLASH_SMEM);

    const int M = B_ * S_;                        // 4096
    dim3 gproj(D_ / 128, M / 128);                // (8, 32) = 256 CTAs

    gemm_tc<<<gproj, 256, GEMM_SMEM>>>(query, w_q, b_q, gq, M, D_, D_);
    gemm_tc<<<gproj, 256, GEMM_SMEM>>>(key,   w_k, b_k, gk, M, D_, D_);
    gemm_tc<<<gproj, 256, GEMM_SMEM>>>(value, w_v, b_v, gv, M, D_, D_);

    dim3 gflash(S_ / 128, H_, B_);                // (16, 16, 2) = 512 CTAs
    flash_tc<<<gflash, 256, FLASH_SMEM>>>(gq, gk, gv, mask, gc);

    gemm_tc<<<gproj, 256, GEMM_SMEM>>>(gc, w_o, b_o, (float*)d_out, M, D_, D_);
}